// round 4
// baseline (speedup 1.0000x reference)
#include <cuda_runtime.h>
#include <cuda_bf16.h>
#include <cstdint>

#define N_NODES 100000
#define D 64

// Scratch (no allocations allowed; __device__ globals are the sanctioned path).
__device__ __align__(16) float g_buf[N_NODES * D];    // g = (x @ W^T) * dinv[row]
__device__ __align__(16) float acc_buf[N_NODES * D];  // accumulator (init = g → self loop folded)
__device__ __align__(16) float h1_buf[N_NODES * D];   // layer-1 output
__device__ float dinv_buf[N_NODES];
__device__ float deg_buf[N_NODES];
__device__ int g_is64;  // 1 if edge_index buffer is int64, 0 if int32

// ---------------------------------------------------------------------------
// Edge dtype probe: int64 little-endian values < 2^31 have every odd 32-bit
// word == 0; int32 node ids at odd positions are ~never all zero over 2048
// samples. Sets g_is64 once; all edge readers dispatch through it.
// ---------------------------------------------------------------------------
__global__ void detect_kernel(const int* __restrict__ w, long long nwords) {
    __shared__ int nz;
    if (threadIdx.x == 0) nz = 0;
    __syncthreads();
    int local = 0;
    for (int i = threadIdx.x; i < 2048; i += 256) {
        long long idx = 2LL * i + 1;
        if (idx < nwords && w[idx] != 0) local = 1;
    }
    if (local) atomicAdd(&nz, 1);
    __syncthreads();
    if (threadIdx.x == 0) g_is64 = (nz == 0) ? 1 : 0;
}

// pos in [0, 2E): flat position in the edge_index buffer.
__device__ __forceinline__ int edge_idx(const void* __restrict__ ei, long long pos) {
    if (g_is64) return (int)((const long long*)ei)[pos];
    return ((const int*)ei)[pos];
}

// ---------------------------------------------------------------------------
// Degree / dinv
// ---------------------------------------------------------------------------
__global__ void deg_zero_kernel() {
    int i = blockIdx.x * blockDim.x + threadIdx.x;
    if (i < N_NODES) deg_buf[i] = 0.0f;
}

__global__ void deg_count_kernel(const void* __restrict__ ei, int E) {
    int e = blockIdx.x * blockDim.x + threadIdx.x;
    if (e < E) {
        int d = edge_idx(ei, (long long)E + e);  // dst half
        atomicAdd(&deg_buf[d], 1.0f);
    }
}

__global__ void deg_finalize_kernel() {
    int i = blockIdx.x * blockDim.x + threadIdx.x;
    if (i < N_NODES) dinv_buf[i] = rsqrtf(deg_buf[i] + 1.0f);  // +1 = self loop
}

// ---------------------------------------------------------------------------
// GEMM: g[row] = (x[row] @ W^T) * dinv[row]; also acc = g (self-loop init).
// 64x64 tile per block, 256 threads, 4x4 register blocking, padded smem.
// ---------------------------------------------------------------------------
__global__ __launch_bounds__(256) void gemm_scale_kernel(
    const float* __restrict__ x, const float* __restrict__ W) {
    __shared__ float4 xs[64 * 17];
    __shared__ float4 Ws[64 * 17];

    int tid = threadIdx.x;
    int rowBase = blockIdx.x * 64;

    const float4* W4 = (const float4*)W;
    for (int i = tid; i < 1024; i += 256) {
        int j = i >> 4, kk = i & 15;
        Ws[j * 17 + kk] = W4[i];
    }
    const float4* x4 = (const float4*)x;
    for (int i = tid; i < 1024; i += 256) {
        int r = i >> 4, kk = i & 15;
        if (rowBase + r < N_NODES)
            xs[r * 17 + kk] = x4[(size_t)(rowBase + r) * 16 + kk];
    }
    __syncthreads();

    int tx = tid & 15;  // cols tx*4 .. tx*4+3
    int ty = tid >> 4;  // rows ty*4 .. ty*4+3

    float acc[4][4];
#pragma unroll
    for (int i = 0; i < 4; i++)
#pragma unroll
        for (int j = 0; j < 4; j++) acc[i][j] = 0.0f;

#pragma unroll
    for (int kk = 0; kk < 16; kk++) {
        float4 xv[4], wv[4];
#pragma unroll
        for (int l = 0; l < 4; l++) xv[l] = xs[(ty * 4 + l) * 17 + kk];
#pragma unroll
        for (int l = 0; l < 4; l++) wv[l] = Ws[(tx * 4 + l) * 17 + kk];
#pragma unroll
        for (int i = 0; i < 4; i++)
#pragma unroll
            for (int j = 0; j < 4; j++) {
                acc[i][j] = fmaf(xv[i].x, wv[j].x, acc[i][j]);
                acc[i][j] = fmaf(xv[i].y, wv[j].y, acc[i][j]);
                acc[i][j] = fmaf(xv[i].z, wv[j].z, acc[i][j]);
                acc[i][j] = fmaf(xv[i].w, wv[j].w, acc[i][j]);
            }
    }

#pragma unroll
    for (int i = 0; i < 4; i++) {
        int row = rowBase + ty * 4 + i;
        if (row < N_NODES) {
            float di = dinv_buf[row];
            float4 v;
            v.x = acc[i][0] * di;
            v.y = acc[i][1] * di;
            v.z = acc[i][2] * di;
            v.w = acc[i][3] * di;
            size_t off = (size_t)row * 16 + tx;
            ((float4*)g_buf)[off] = v;
            ((float4*)acc_buf)[off] = v;  // self-loop pre-seeded
        }
    }
}

// ---------------------------------------------------------------------------
// Scatter: acc[dst] += g[src] via red.global.add.v4.f32.
// 16 threads per edge, one float4 each. cvta.to.global required.
// ---------------------------------------------------------------------------
__global__ __launch_bounds__(256) void scatter_kernel(
    const void* __restrict__ ei, int E) {
    int gid = blockIdx.x * blockDim.x + threadIdx.x;
    int e = gid >> 4;
    if (e >= E) return;
    int q = gid & 15;
    int s = edge_idx(ei, e);
    int d = edge_idx(ei, (long long)E + e);
    float4 v = ((const float4*)g_buf)[(size_t)s * 16 + q];
    float* ap = acc_buf + (size_t)d * 64 + q * 4;
    asm volatile(
        "{\n\t"
        ".reg .u64 gaddr;\n\t"
        "cvta.to.global.u64 gaddr, %0;\n\t"
        "red.global.add.v4.f32 [gaddr], {%1,%2,%3,%4};\n\t"
        "}"
        :: "l"(ap), "f"(v.x), "f"(v.y), "f"(v.z), "f"(v.w)
        : "memory");
}

// ---------------------------------------------------------------------------
// Finalize: out[i] = dinv[i] * acc[i] + b
// ---------------------------------------------------------------------------
__global__ __launch_bounds__(256) void finalize_kernel(
    const float* __restrict__ b, float* __restrict__ out) {
    int gid = blockIdx.x * blockDim.x + threadIdx.x;
    if (gid >= N_NODES * 16) return;
    int i = gid >> 4;
    int q = gid & 15;
    float di = dinv_buf[i];
    float4 a = ((const float4*)acc_buf)[(size_t)i * 16 + q];
    float4 bb = ((const float4*)b)[q];
    float4 o;
    o.x = fmaf(di, a.x, bb.x);
    o.y = fmaf(di, a.y, bb.y);
    o.z = fmaf(di, a.z, bb.z);
    o.w = fmaf(di, a.w, bb.w);
    ((float4*)out)[gid] = o;
}

// ---------------------------------------------------------------------------
extern "C" void kernel_launch(void* const* d_in, const int* in_sizes, int n_in,
                              void* d_out, int out_size) {
    const float* x = (const float*)d_in[0];
    const void* ei = d_in[1];
    const float* W1 = (const float*)d_in[2];
    const float* b1 = (const float*)d_in[3];
    const float* W2 = (const float*)d_in[4];
    const float* b2 = (const float*)d_in[5];
    float* out = (float*)d_out;

    int E = in_sizes[1] / 2;  // element count is dtype-independent

    int nThreads = 256;
    int nodeBlocks = (N_NODES + nThreads - 1) / nThreads;
    int edgeBlocks = (E + nThreads - 1) / nThreads;
    int gemmBlocks = (N_NODES + 63) / 64;
    int scatBlocks = (int)(((long long)E * 16 + nThreads - 1) / nThreads);
    int finBlocks = (N_NODES * 16 + nThreads - 1) / nThreads;

    // Probe edge dtype (int32 words visible either way; nwords conservative
    // lower bound = 2E, valid for both dtypes).
    detect_kernel<<<1, 256>>>((const int*)ei, (long long)E * 2);

    // Degree / dinv (once; shared by both layers)
    deg_zero_kernel<<<nodeBlocks, nThreads>>>();
    deg_count_kernel<<<edgeBlocks, nThreads>>>(ei, E);
    deg_finalize_kernel<<<nodeBlocks, nThreads>>>();

    // Layer 1
    gemm_scale_kernel<<<gemmBlocks, nThreads>>>(x, W1);
    scatter_kernel<<<scatBlocks, nThreads>>>(ei, E);
    finalize_kernel<<<finBlocks, nThreads>>>(b1, h1_buf);

    // Layer 2
    gemm_scale_kernel<<<gemmBlocks, nThreads>>>(h1_buf, W2);
    scatter_kernel<<<scatBlocks, nThreads>>>(ei, E);
    finalize_kernel<<<finBlocks, nThreads>>>(b2, out);
}

// round 5
// speedup vs baseline: 1.3669x; 1.3669x over previous
#include <cuda_runtime.h>
#include <cuda_bf16.h>
#include <cstdint>

#define N_NODES 100000
#define D 64
#define E_MAX 1700000
#define SCAN_BLK 512

// Scratch (__device__ globals: the sanctioned allocation-free path).
__device__ __align__(16) float g_buf[N_NODES * D];   // g = (x @ W^T) * dinv[row]
__device__ __align__(16) float h1_buf[N_NODES * D];  // layer-1 output
__device__ float dinv_buf[N_NODES];
__device__ int cnt_buf[N_NODES];       // in-degree histogram
__device__ int row_start[N_NODES + 1]; // CSR row offsets (by dst)
__device__ int cursor_buf[N_NODES];    // placement cursors
__device__ int csr_src[E_MAX];         // CSR column (src) indices
__device__ int block_sums[(N_NODES + SCAN_BLK - 1) / SCAN_BLK];
__device__ int g_is64;                 // edge_index dtype flag

// ---------------------------------------------------------------------------
// Edge dtype probe: int64 LE values < 2^31 -> every odd 32-bit word is 0.
// ---------------------------------------------------------------------------
__global__ void detect_kernel(const int* __restrict__ w, long long nwords) {
    __shared__ int nz;
    if (threadIdx.x == 0) nz = 0;
    __syncthreads();
    int local = 0;
    for (int i = threadIdx.x; i < 2048; i += 256) {
        long long idx = 2LL * i + 1;
        if (idx < nwords && w[idx] != 0) local = 1;
    }
    if (local) atomicAdd(&nz, 1);
    __syncthreads();
    if (threadIdx.x == 0) g_is64 = (nz == 0) ? 1 : 0;
}

__device__ __forceinline__ int edge_idx(const void* __restrict__ ei, long long pos) {
    if (g_is64) return (int)((const long long*)ei)[pos];
    return ((const int*)ei)[pos];
}

// ---------------------------------------------------------------------------
// CSR build: histogram -> exclusive scan (3 kernels) -> placement
// ---------------------------------------------------------------------------
__global__ void hist_zero_kernel() {
    int i = blockIdx.x * blockDim.x + threadIdx.x;
    if (i < N_NODES) cnt_buf[i] = 0;
}

__global__ void hist_kernel(const void* __restrict__ ei, int E) {
    int e = blockIdx.x * blockDim.x + threadIdx.x;
    if (e < E) atomicAdd(&cnt_buf[edge_idx(ei, (long long)E + e)], 1);
}

// Per-block exclusive scan; writes local prefix + block total.
__global__ __launch_bounds__(SCAN_BLK) void scan_block_kernel() {
    __shared__ int s[SCAN_BLK];
    int i = blockIdx.x * SCAN_BLK + threadIdx.x;
    int v = (i < N_NODES) ? cnt_buf[i] : 0;
    s[threadIdx.x] = v;
    __syncthreads();
    // Hillis-Steele inclusive scan
#pragma unroll
    for (int off = 1; off < SCAN_BLK; off <<= 1) {
        int t = (threadIdx.x >= off) ? s[threadIdx.x - off] : 0;
        __syncthreads();
        s[threadIdx.x] += t;
        __syncthreads();
    }
    if (i < N_NODES) row_start[i] = s[threadIdx.x] - v;  // exclusive
    if (threadIdx.x == SCAN_BLK - 1) block_sums[blockIdx.x] = s[threadIdx.x];
}

// Single-block exclusive scan of the block sums (nb <= 512).
__global__ __launch_bounds__(SCAN_BLK) void scan_tops_kernel(int nb) {
    __shared__ int s[SCAN_BLK];
    int v = (threadIdx.x < nb) ? block_sums[threadIdx.x] : 0;
    s[threadIdx.x] = v;
    __syncthreads();
#pragma unroll
    for (int off = 1; off < SCAN_BLK; off <<= 1) {
        int t = (threadIdx.x >= off) ? s[threadIdx.x - off] : 0;
        __syncthreads();
        s[threadIdx.x] += t;
        __syncthreads();
    }
    if (threadIdx.x < nb) block_sums[threadIdx.x] = s[threadIdx.x] - v;
}

__global__ void scan_add_kernel(int E) {
    int i = blockIdx.x * blockDim.x + threadIdx.x;
    if (i < N_NODES) {
        int r = row_start[i] + block_sums[i / SCAN_BLK];
        row_start[i] = r;
        cursor_buf[i] = r;
        // dinv while we're here (cnt still valid): deg + self loop
        dinv_buf[i] = rsqrtf((float)cnt_buf[i] + 1.0f);
    }
    if (i == 0) row_start[N_NODES] = E;
}

__global__ void place_kernel(const void* __restrict__ ei, int E) {
    int e = blockIdx.x * blockDim.x + threadIdx.x;
    if (e < E) {
        int s = edge_idx(ei, e);
        int d = edge_idx(ei, (long long)E + e);
        int pos = atomicAdd(&cursor_buf[d], 1);
        csr_src[pos] = s;
    }
}

// ---------------------------------------------------------------------------
// GEMM: g[row] = (x[row] @ W^T) * dinv[row].
// 64x64 tile per block, 256 threads, 4x4 register blocking, padded smem.
// ---------------------------------------------------------------------------
__global__ __launch_bounds__(256) void gemm_scale_kernel(
    const float* __restrict__ x, const float* __restrict__ W) {
    __shared__ float4 xs[64 * 17];
    __shared__ float4 Ws[64 * 17];

    int tid = threadIdx.x;
    int rowBase = blockIdx.x * 64;

    const float4* W4 = (const float4*)W;
    for (int i = tid; i < 1024; i += 256) {
        int j = i >> 4, kk = i & 15;
        Ws[j * 17 + kk] = W4[i];
    }
    const float4* x4 = (const float4*)x;
    for (int i = tid; i < 1024; i += 256) {
        int r = i >> 4, kk = i & 15;
        if (rowBase + r < N_NODES)
            xs[r * 17 + kk] = x4[(size_t)(rowBase + r) * 16 + kk];
    }
    __syncthreads();

    int tx = tid & 15;
    int ty = tid >> 4;

    float acc[4][4];
#pragma unroll
    for (int i = 0; i < 4; i++)
#pragma unroll
        for (int j = 0; j < 4; j++) acc[i][j] = 0.0f;

#pragma unroll
    for (int kk = 0; kk < 16; kk++) {
        float4 xv[4], wv[4];
#pragma unroll
        for (int l = 0; l < 4; l++) xv[l] = xs[(ty * 4 + l) * 17 + kk];
#pragma unroll
        for (int l = 0; l < 4; l++) wv[l] = Ws[(tx * 4 + l) * 17 + kk];
#pragma unroll
        for (int i = 0; i < 4; i++)
#pragma unroll
            for (int j = 0; j < 4; j++) {
                acc[i][j] = fmaf(xv[i].x, wv[j].x, acc[i][j]);
                acc[i][j] = fmaf(xv[i].y, wv[j].y, acc[i][j]);
                acc[i][j] = fmaf(xv[i].z, wv[j].z, acc[i][j]);
                acc[i][j] = fmaf(xv[i].w, wv[j].w, acc[i][j]);
            }
    }

#pragma unroll
    for (int i = 0; i < 4; i++) {
        int row = rowBase + ty * 4 + i;
        if (row < N_NODES) {
            float di = dinv_buf[row];
            float4 v;
            v.x = acc[i][0] * di;
            v.y = acc[i][1] * di;
            v.z = acc[i][2] * di;
            v.w = acc[i][3] * di;
            ((float4*)g_buf)[(size_t)row * 16 + tx] = v;
        }
    }
}

// ---------------------------------------------------------------------------
// Pull aggregation + fused finalize: atomics-free.
// 16 threads per dst node; each owns one float4 of the 64-float row.
// out[d] = dinv[d] * (sum_{s in N(d)} g[s] + g[d]) + b
// ---------------------------------------------------------------------------
__global__ __launch_bounds__(256) void pull_kernel(
    const float* __restrict__ b, float* __restrict__ out) {
    int gid = blockIdx.x * blockDim.x + threadIdx.x;
    int node = gid >> 4;
    if (node >= N_NODES) return;
    int q = gid & 15;

    const float4* g4 = (const float4*)g_buf;
    int beg = row_start[node];
    int end = row_start[node + 1];

    // self loop seed
    float4 acc = g4[(size_t)node * 16 + q];

    int e = beg;
    // unroll-by-2 for memory-level parallelism
    for (; e + 1 < end; e += 2) {
        int s0 = csr_src[e];
        int s1 = csr_src[e + 1];
        float4 v0 = g4[(size_t)s0 * 16 + q];
        float4 v1 = g4[(size_t)s1 * 16 + q];
        acc.x += v0.x + v1.x;
        acc.y += v0.y + v1.y;
        acc.z += v0.z + v1.z;
        acc.w += v0.w + v1.w;
    }
    if (e < end) {
        int s0 = csr_src[e];
        float4 v0 = g4[(size_t)s0 * 16 + q];
        acc.x += v0.x;
        acc.y += v0.y;
        acc.z += v0.z;
        acc.w += v0.w;
    }

    float di = dinv_buf[node];
    float4 bb = ((const float4*)b)[q];
    float4 o;
    o.x = fmaf(di, acc.x, bb.x);
    o.y = fmaf(di, acc.y, bb.y);
    o.z = fmaf(di, acc.z, bb.z);
    o.w = fmaf(di, acc.w, bb.w);
    ((float4*)out)[gid] = o;
}

// ---------------------------------------------------------------------------
extern "C" void kernel_launch(void* const* d_in, const int* in_sizes, int n_in,
                              void* d_out, int out_size) {
    const float* x = (const float*)d_in[0];
    const void* ei = d_in[1];
    const float* W1 = (const float*)d_in[2];
    const float* b1 = (const float*)d_in[3];
    const float* W2 = (const float*)d_in[4];
    const float* b2 = (const float*)d_in[5];
    float* out = (float*)d_out;

    int E = in_sizes[1] / 2;

    int nThreads = 256;
    int nodeBlocks = (N_NODES + nThreads - 1) / nThreads;
    int edgeBlocks = (E + nThreads - 1) / nThreads;
    int gemmBlocks = (N_NODES + 63) / 64;
    int pullBlocks = (N_NODES * 16 + nThreads - 1) / nThreads;
    int scanBlocks = (N_NODES + SCAN_BLK - 1) / SCAN_BLK;

    // dtype probe
    detect_kernel<<<1, 256>>>((const int*)ei, (long long)E * 2);

    // CSR build (also computes dinv)
    hist_zero_kernel<<<nodeBlocks, nThreads>>>();
    hist_kernel<<<edgeBlocks, nThreads>>>(ei, E);
    scan_block_kernel<<<scanBlocks, SCAN_BLK>>>();
    scan_tops_kernel<<<1, SCAN_BLK>>>(scanBlocks);
    scan_add_kernel<<<nodeBlocks, nThreads>>>(E);
    place_kernel<<<edgeBlocks, nThreads>>>(ei, E);

    // Layer 1
    gemm_scale_kernel<<<gemmBlocks, nThreads>>>(x, W1);
    pull_kernel<<<pullBlocks, nThreads>>>(b1, h1_buf);

    // Layer 2
    gemm_scale_kernel<<<gemmBlocks, nThreads>>>(h1_buf, W2);
    pull_kernel<<<pullBlocks, nThreads>>>(b2, out);
}